// round 15
// baseline (speedup 1.0000x reference)
#include <cuda_runtime.h>
#include <cuda_bf16.h>
#include <cstdint>

#define NN 50000
#define NE 800000
#define SCAN_BLOCKS 196
#define SCAN_CHUNK  ((NN + SCAN_BLOCKS - 1) / SCAN_BLOCKS)   // 256

// ------------------------- scratch (device globals) -------------------------
__device__ float    g_feat[NN * 256];
__device__ float    g_h[NN * 256];
__device__ float    g_el[NN * 4];
__device__ float    g_er[NN * 4];
__device__ float    g_el2[NN * 4];
__device__ float    g_er2[NN * 4];
__device__ int      g_cnt[NN];
__device__ int      g_rp[NN + 1];
__device__ int      g_cur[NN];
__device__ int      g_csrc[NE];
__device__ int      g_bsum[SCAN_BLOCKS];
__device__ __nv_bfloat16 g_Ahi[NN * 256];
__device__ __nv_bfloat16 g_Alo[NN * 256];
__device__ __nv_bfloat16 g_Whi[256 * 256];
__device__ __nv_bfloat16 g_Wlo[256 * 256];
__device__ __nv_bfloat16 g_Whi2[256 * 256];
__device__ __nv_bfloat16 g_Wlo2[256 * 256];

__device__ __forceinline__ uint32_t smem_u32(const void* p) {
    uint32_t a;
    asm("{ .reg .u64 t; cvta.to.shared.u64 t, %1; cvt.u32.u64 %0, t; }" : "=r"(a) : "l"(p));
    return a;
}
__device__ __forceinline__ void cpa16(uint32_t s, const void* g) {
    asm volatile("cp.async.cg.shared.global [%0], [%1], 16;"
                 :: "r"(s), "l"(__cvta_generic_to_global(g)));
}

// ------------------------- CSR build ----------------------------------------
__global__ void init_cnt(int* __restrict__ cnt) {
    int i = blockIdx.x * blockDim.x + threadIdx.x;
    if (i < NN) cnt[i] = 0;
}
__global__ void hist_kernel(const int* __restrict__ dst, int* __restrict__ cnt) {
    int i = blockIdx.x * blockDim.x + threadIdx.x;
    if (i < NE) atomicAdd(&cnt[dst[i]], 1);
}
__global__ void scan_p1(const int* __restrict__ cnt, int* __restrict__ bsum) {
    __shared__ int red[256];
    int b = blockIdx.x, t = threadIdx.x;
    int beg = b * SCAN_CHUNK;
    int end = beg + SCAN_CHUNK; if (end > NN) end = NN;
    int s = 0;
    for (int i = beg + t; i < end; i += 256) s += cnt[i];
    red[t] = s;
    __syncthreads();
    for (int d = 128; d; d >>= 1) {
        if (t < d) red[t] += red[t + d];
        __syncthreads();
    }
    if (t == 0) bsum[b] = red[0];
}
__global__ void scan_p2(int* __restrict__ bsum) {
    __shared__ int v[256];
    int t = threadIdx.x;
    v[t] = (t < SCAN_BLOCKS) ? bsum[t] : 0;
    __syncthreads();
#pragma unroll
    for (int d = 1; d < 256; d <<= 1) {
        int x = (t >= d) ? v[t - d] : 0;
        __syncthreads();
        v[t] += x;
        __syncthreads();
    }
    if (t < SCAN_BLOCKS) bsum[t] = (t > 0) ? v[t - 1] : 0;
}
__global__ void scan_p3(const int* __restrict__ cnt, const int* __restrict__ bsum,
                        int* __restrict__ rp, int* __restrict__ cur) {
    int b = blockIdx.x, t = threadIdx.x;
    if (t != 0) return;
    int beg = b * SCAN_CHUNK;
    int end = beg + SCAN_CHUNK; if (end > NN) end = NN;
    int off = bsum[b];
    for (int i = beg; i < end; i++) { rp[i] = off; cur[i] = off; off += cnt[i]; }
    if (b == SCAN_BLOCKS - 1) rp[NN] = NE;
}
__global__ void scatter_kernel(const int* __restrict__ src, const int* __restrict__ dst,
                               int* __restrict__ cur, int* __restrict__ csrc) {
    int i = blockIdx.x * blockDim.x + threadIdx.x;
    if (i >= NE) return;
    int p = atomicAdd(&cur[dst[i]], 1);
    csrc[p] = src[i];
}

// ---- merged: convA (layer-0 inputs) + convW (W0) + zero el/er --------------
__global__ void convAW_kernel(const float* __restrict__ A, __nv_bfloat16* __restrict__ Ahi,
                              __nv_bfloat16* __restrict__ Alo, int count4,
                              const float* __restrict__ W, __nv_bfloat16* __restrict__ thi,
                              __nv_bfloat16* __restrict__ tlo, int kin,
                              float* __restrict__ el, float* __restrict__ er) {
    int i = blockIdx.x * blockDim.x + threadIdx.x;
    int gs = gridDim.x * blockDim.x;
    for (int j = i; j < NN * 4; j += gs) { el[j] = 0.f; er[j] = 0.f; }
    for (int j = i; j < kin * 256; j += gs) {
        int k = j >> 8, o = j & 255;
        float v = W[j];
        __nv_bfloat16 hh = __float2bfloat16(v);
        thi[o * kin + k] = hh;
        tlo[o * kin + k] = __float2bfloat16(v - __bfloat162float(hh));
    }
    if (i >= count4) return;
    float4 v = ((const float4*)A)[i];
    __nv_bfloat16 h0 = __float2bfloat16(v.x), h1 = __float2bfloat16(v.y);
    __nv_bfloat16 h2 = __float2bfloat16(v.z), h3 = __float2bfloat16(v.w);
    __nv_bfloat16 l0 = __float2bfloat16(v.x - __bfloat162float(h0));
    __nv_bfloat16 l1 = __float2bfloat16(v.y - __bfloat162float(h1));
    __nv_bfloat16 l2 = __float2bfloat16(v.z - __bfloat162float(h2));
    __nv_bfloat16 l3 = __float2bfloat16(v.w - __bfloat162float(h3));
    __nv_bfloat162* ph = (__nv_bfloat162*)Ahi;
    __nv_bfloat162* pl = (__nv_bfloat162*)Alo;
    ph[i * 2 + 0] = __nv_bfloat162(h0, h1);
    ph[i * 2 + 1] = __nv_bfloat162(h2, h3);
    pl[i * 2 + 0] = __nv_bfloat162(l0, l1);
    pl[i * 2 + 1] = __nv_bfloat162(l2, l3);
}

__global__ void convW_kernel(const float* __restrict__ W, __nv_bfloat16* __restrict__ thi,
                             __nv_bfloat16* __restrict__ tlo, int kin,
                             float* __restrict__ el, float* __restrict__ er) {
    int i = blockIdx.x * blockDim.x + threadIdx.x;
    for (int j = i; j < NN * 4; j += gridDim.x * blockDim.x) { el[j] = 0.f; er[j] = 0.f; }
    if (i >= kin * 256) return;
    int k = i >> 8, o = i & 255;
    float v = W[i];
    __nv_bfloat16 h = __float2bfloat16(v);
    thi[o * kin + k] = h;
    tlo[o * kin + k] = __float2bfloat16(v - __bfloat162float(h));
}

// ------- HMMA GEMM, cp.async double-buffered, fused el/er epilogue ----------
#define HMMA_STAGE 65536
#define HMMA_SMEM  (2 * HMMA_STAGE)

__device__ __forceinline__ void mma16816(float* c, const uint32_t* a, const uint32_t* b) {
    asm volatile(
        "mma.sync.aligned.m16n8k16.row.col.f32.bf16.bf16.f32 "
        "{%0,%1,%2,%3}, {%4,%5,%6,%7}, {%8,%9}, {%0,%1,%2,%3};"
        : "+f"(c[0]), "+f"(c[1]), "+f"(c[2]), "+f"(c[3])
        : "r"(a[0]), "r"(a[1]), "r"(a[2]), "r"(a[3]), "r"(b[0]), "r"(b[1]));
}
__device__ __forceinline__ void ldsm4(uint32_t* r, uint32_t addr) {
    asm volatile("ldmatrix.sync.aligned.m8n8.x4.shared.b16 {%0,%1,%2,%3}, [%4];"
                 : "=r"(r[0]), "=r"(r[1]), "=r"(r[2]), "=r"(r[3]) : "r"(addr));
}

__global__ void __launch_bounds__(256, 1) hmma_gemm(
    const __nv_bfloat16* __restrict__ Ahi, const __nv_bfloat16* __restrict__ Alo,
    const __nv_bfloat16* __restrict__ Bhi, const __nv_bfloat16* __restrict__ Blo,
    float* __restrict__ C, int n, int kin,
    const float* __restrict__ alv, const float* __restrict__ arv,
    float* __restrict__ elo, float* __restrict__ ero)
{
    extern __shared__ char smem[];
    int tid = threadIdx.x, wid = tid >> 5, lane = tid & 31;
    int baseM = blockIdx.y * 128;
    int baseN = blockIdx.x * 128;
    int wm = wid >> 2, wn = wid & 3;

    float acc[4][4][4];
#pragma unroll
    for (int i = 0; i < 4; i++)
#pragma unroll
        for (int j = 0; j < 4; j++)
#pragma unroll
            for (int q = 0; q < 4; q++) acc[i][j][q] = 0.f;

    int arow = wm * 64 + (lane & 15);
    int ahalf16 = (lane >> 4) * 16;
    int brow = wn * 32 + ((lane >> 4) << 3) + (lane & 7);
    int bhalf16 = ((lane >> 3) & 1) * 16;

    uint32_t sb = smem_u32(smem);
    int nchunks = kin >> 6;

    auto load_chunk = [&](int kc, int stg) {
        uint32_t base = sb + stg * HMMA_STAGE;
#pragma unroll
        for (int it = 0; it < 4; it++) {
            int c = it * 256 + tid;
            int row = c >> 3, cj = c & 7;
            uint32_t off = row * 128 + ((cj * 16) ^ ((row & 7) << 4));
            int gr = baseM + row;
            if (gr < n) {
                size_t gi = (size_t)gr * kin + kc * 64 + cj * 8;
                cpa16(base + off, Ahi + gi);
                cpa16(base + 16384 + off, Alo + gi);
            } else {
                *(uint4*)(smem + stg * HMMA_STAGE + off) = make_uint4(0, 0, 0, 0);
                *(uint4*)(smem + stg * HMMA_STAGE + 16384 + off) = make_uint4(0, 0, 0, 0);
            }
            size_t wi = (size_t)(baseN + row) * kin + kc * 64 + cj * 8;
            cpa16(base + 32768 + off, Bhi + wi);
            cpa16(base + 49152 + off, Blo + wi);
        }
        asm volatile("cp.async.commit_group;" ::: "memory");
    };

    load_chunk(0, 0);
    for (int kc = 0; kc < nchunks; kc++) {
        if (kc + 1 < nchunks) {
            load_chunk(kc + 1, (kc + 1) & 1);
            asm volatile("cp.async.wait_group 1;" ::: "memory");
        } else {
            asm volatile("cp.async.wait_group 0;" ::: "memory");
        }
        __syncthreads();

        uint32_t sA  = sb + (kc & 1) * HMMA_STAGE;
        uint32_t sAl = sA + 16384;
        uint32_t sW  = sA + 32768;
        uint32_t sWl = sA + 49152;
#pragma unroll
        for (int s = 0; s < 4; s++) {
            uint32_t ah[4][4], al_[4][4], bh[2][4], bl[2][4];
#pragma unroll
            for (int mi = 0; mi < 4; mi++) {
                int r = arow + mi * 16;
                uint32_t off = r * 128 + ((s * 32 + ahalf16) ^ ((r & 7) << 4));
                ldsm4(ah[mi], sA + off);
                ldsm4(al_[mi], sAl + off);
            }
#pragma unroll
            for (int p = 0; p < 2; p++) {
                int r = brow + p * 16;
                uint32_t off = r * 128 + ((s * 32 + bhalf16) ^ ((r & 7) << 4));
                ldsm4(bh[p], sW + off);
                ldsm4(bl[p], sWl + off);
            }
#pragma unroll
            for (int mi = 0; mi < 4; mi++)
#pragma unroll
                for (int p = 0; p < 2; p++)
#pragma unroll
                    for (int q = 0; q < 2; q++) {
                        int t = p * 2 + q;
                        mma16816(acc[mi][t], ah[mi], &bh[p][q * 2]);
                        mma16816(acc[mi][t], ah[mi], &bl[p][q * 2]);
                        mma16816(acc[mi][t], al_[mi], &bh[p][q * 2]);
                    }
        }
        __syncthreads();
    }

    int g = lane >> 2, t4 = lane & 3;

#pragma unroll
    for (int mi = 0; mi < 4; mi++) {
        int r0 = baseM + wm * 64 + mi * 16 + g;
        int r1 = r0 + 8;
#pragma unroll
        for (int t = 0; t < 4; t++) {
            int col = baseN + wn * 32 + t * 8 + t4 * 2;
            if (r0 < n) *(float2*)(C + (size_t)r0 * 256 + col) = make_float2(acc[mi][t][0], acc[mi][t][1]);
            if (r1 < n) *(float2*)(C + (size_t)r1 * 256 + col) = make_float2(acc[mi][t][2], acc[mi][t][3]);
        }
    }

    int hh = (baseN + wn * 32) >> 6;
    float av[4][2], rv[4][2];
#pragma unroll
    for (int t = 0; t < 4; t++) {
        int col = baseN + wn * 32 + t * 8 + t4 * 2;
        av[t][0] = alv[col]; av[t][1] = alv[col + 1];
        rv[t][0] = arv[col]; rv[t][1] = arv[col + 1];
    }
#pragma unroll
    for (int mi = 0; mi < 4; mi++) {
        float e0 = 0.f, e1 = 0.f, f0 = 0.f, f1 = 0.f;
#pragma unroll
        for (int t = 0; t < 4; t++) {
            e0 += acc[mi][t][0] * av[t][0] + acc[mi][t][1] * av[t][1];
            e1 += acc[mi][t][2] * av[t][0] + acc[mi][t][3] * av[t][1];
            f0 += acc[mi][t][0] * rv[t][0] + acc[mi][t][1] * rv[t][1];
            f1 += acc[mi][t][2] * rv[t][0] + acc[mi][t][3] * rv[t][1];
        }
#pragma unroll
        for (int o = 1; o <= 2; o <<= 1) {
            e0 += __shfl_xor_sync(0xffffffffu, e0, o);
            e1 += __shfl_xor_sync(0xffffffffu, e1, o);
            f0 += __shfl_xor_sync(0xffffffffu, f0, o);
            f1 += __shfl_xor_sync(0xffffffffu, f1, o);
        }
        if (t4 == 0) {
            int r0 = baseM + wm * 64 + mi * 16 + g;
            int r1 = r0 + 8;
            if (r0 < n) { atomicAdd(&elo[r0 * 4 + hh], e0); atomicAdd(&ero[r0 * 4 + hh], f0); }
            if (r1 < n) { atomicAdd(&elo[r1 * 4 + hh], e1); atomicAdd(&ero[r1 * 4 + hh], f1); }
        }
    }
}

// --------- small GEMM for layer 2 (kin=256, kout=16) + fused el/er ----------
__global__ void gemm16(const float* __restrict__ A, const float* __restrict__ W,
                       float* __restrict__ C, int n,
                       const float* __restrict__ alv, const float* __restrict__ arv,
                       float* __restrict__ elo, float* __restrict__ ero) {
    __shared__ float As[16][256];
    __shared__ float Wt[16][260];
    int tid = threadIdx.x;
    int base = blockIdx.x * 16;
    for (int i = tid; i < 4096; i += 256) {
        int k = i >> 4, oi = i & 15;
        Wt[oi][k] = W[i];
    }
    for (int i = tid; i < 1024; i += 256) {
        int r = i >> 6, c4 = i & 63;
        float4 v = make_float4(0.f, 0.f, 0.f, 0.f);
        if (base + r < n) v = ((const float4*)(A + (size_t)(base + r) * 256))[c4];
        ((float4*)&As[r][0])[c4] = v;
    }
    __syncthreads();
    int ni = tid >> 4, oi = tid & 15;
    float acc = 0.f;
#pragma unroll 16
    for (int k4 = 0; k4 < 64; k4++) {
        float4 a = ((const float4*)&As[ni][0])[k4];
        float4 w = *(const float4*)&Wt[oi][k4 * 4];
        acc += a.x * w.x + a.y * w.y + a.z * w.z + a.w * w.w;
    }
    if (base + ni < n) C[(size_t)(base + ni) * 16 + oi] = acc;

    float e = acc * alv[oi], f = acc * arv[oi];
#pragma unroll
    for (int o = 8; o; o >>= 1) {
        e += __shfl_xor_sync(0xffffffffu, e, o);
        f += __shfl_xor_sync(0xffffffffu, f, o);
    }
    if (oi == 0 && base + ni < n) { elo[base + ni] = e; ero[base + ni] = f; }
}

// ---- fused softmax + aggregate, H=4, D=64 (ebuf-free, unroll x4) -----------
template <int OUT_BF16>
__global__ void __launch_bounds__(256) gat_fused4(
    const int* __restrict__ rp, const int* __restrict__ cs,
    const float* __restrict__ el, const float* __restrict__ er,
    const float* __restrict__ feat, const float* __restrict__ bias,
    float* __restrict__ outf,
    __nv_bfloat16* __restrict__ outhi, __nv_bfloat16* __restrict__ outlo)
{
    int node = (blockIdx.x * blockDim.x + threadIdx.x) >> 5;
    int lane = threadIdx.x & 31;
    if (node >= NN) return;
    int s0 = rp[node], s1 = rp[node + 1];

    float4 er4 = *(const float4*)&er[node * 4];

    // pass A: sum of exp(leaky(logit)) per head
    float t0 = 0.f, t1 = 0.f, t2 = 0.f, t3 = 0.f;
    for (int i = s0 + lane; i < s1; i += 32) {
        int sn = cs[i];
        float4 lv = *(const float4*)&el[sn * 4];
        lv.x += er4.x; lv.y += er4.y; lv.z += er4.z; lv.w += er4.w;
        lv.x = lv.x > 0.f ? lv.x : 0.2f * lv.x;
        lv.y = lv.y > 0.f ? lv.y : 0.2f * lv.y;
        lv.z = lv.z > 0.f ? lv.z : 0.2f * lv.z;
        lv.w = lv.w > 0.f ? lv.w : 0.2f * lv.w;
        t0 += __expf(lv.x); t1 += __expf(lv.y);
        t2 += __expf(lv.z); t3 += __expf(lv.w);
    }
#pragma unroll
    for (int o = 16; o; o >>= 1) {
        t0 += __shfl_xor_sync(0xffffffffu, t0, o);
        t1 += __shfl_xor_sync(0xffffffffu, t1, o);
        t2 += __shfl_xor_sync(0xffffffffu, t2, o);
        t3 += __shfl_xor_sync(0xffffffffu, t3, o);
    }

    int hl = lane >> 3;
    float sv = hl == 0 ? t0 : hl == 1 ? t1 : hl == 2 ? t2 : t3;
    float erh = hl == 0 ? er4.x : hl == 1 ? er4.y : hl == 2 ? er4.z : er4.w;
    float inv = 1.f / sv;

    // pass C: recompute alpha + gather, unrolled x4 for MLP
    float a0 = 0.f, a1 = 0.f, a2 = 0.f, a3 = 0.f, a4 = 0.f, a5 = 0.f, a6 = 0.f, a7 = 0.f;
    int i = s0;
    for (; i + 4 <= s1; i += 4) {
        int sn0 = cs[i], sn1 = cs[i + 1], sn2 = cs[i + 2], sn3 = cs[i + 3];
        float x0 = el[sn0 * 4 + hl] + erh;
        float x1 = el[sn1 * 4 + hl] + erh;
        float x2 = el[sn2 * 4 + hl] + erh;
        float x3 = el[sn3 * 4 + hl] + erh;
        x0 = x0 > 0.f ? x0 : 0.2f * x0;
        x1 = x1 > 0.f ? x1 : 0.2f * x1;
        x2 = x2 > 0.f ? x2 : 0.2f * x2;
        x3 = x3 > 0.f ? x3 : 0.2f * x3;
        float aa0 = __expf(x0) * inv;
        float aa1 = __expf(x1) * inv;
        float aa2 = __expf(x2) * inv;
        float aa3 = __expf(x3) * inv;
        const float4* fp0 = (const float4*)(feat + (size_t)sn0 * 256 + lane * 8);
        const float4* fp1 = (const float4*)(feat + (size_t)sn1 * 256 + lane * 8);
        const float4* fp2 = (const float4*)(feat + (size_t)sn2 * 256 + lane * 8);
        const float4* fp3 = (const float4*)(feat + (size_t)sn3 * 256 + lane * 8);
        float4 u0 = fp0[0], u1 = fp0[1];
        float4 w0 = fp1[0], w1 = fp1[1];
        float4 y0 = fp2[0], y1 = fp2[1];
        float4 z0 = fp3[0], z1 = fp3[1];
        a0 += aa0 * u0.x + aa1 * w0.x; a1 += aa0 * u0.y + aa1 * w0.y;
        a2 += aa0 * u0.z + aa1 * w0.z; a3 += aa0 * u0.w + aa1 * w0.w;
        a4 += aa0 * u1.x + aa1 * w1.x; a5 += aa0 * u1.y + aa1 * w1.y;
        a6 += aa0 * u1.z + aa1 * w1.z; a7 += aa0 * u1.w + aa1 * w1.w;
        a0 += aa2 * y0.x + aa3 * z0.x; a1 += aa2 * y0.y + aa3 * z0.y;
        a2 += aa2 * y0.z + aa3 * z0.z; a3 += aa2 * y0.w + aa3 * z0.w;
        a4 += aa2 * y1.x + aa3 * z1.x; a5 += aa2 * y1.y + aa3 * z1.y;
        a6 += aa2 * y1.z + aa3 * z1.z; a7 += aa2 * y1.w + aa3 * z1.w;
    }
    for (; i < s1; i++) {
        int sn = cs[i];
        float x = el[sn * 4 + hl] + erh;
        x = x > 0.f ? x : 0.2f * x;
        float a = __expf(x) * inv;
        const float4* fp = (const float4*)(feat + (size_t)sn * 256 + lane * 8);
        float4 v0 = fp[0], v1 = fp[1];
        a0 += a * v0.x; a1 += a * v0.y; a2 += a * v0.z; a3 += a * v0.w;
        a4 += a * v1.x; a5 += a * v1.y; a6 += a * v1.z; a7 += a * v1.w;
    }
    const float4* bp = (const float4*)(bias + lane * 8);
    float4 b0 = bp[0], b1 = bp[1];
    float r[8] = { a0 + b0.x, a1 + b0.y, a2 + b0.z, a3 + b0.w,
                   a4 + b1.x, a5 + b1.y, a6 + b1.z, a7 + b1.w };
    if (OUT_BF16) {
        __nv_bfloat16 hi[8], lo[8];
#pragma unroll
        for (int q = 0; q < 8; q++) {
            hi[q] = __float2bfloat16(r[q]);
            lo[q] = __float2bfloat16(r[q] - __bfloat162float(hi[q]));
        }
        *(uint4*)(outhi + (size_t)node * 256 + lane * 8) = *(const uint4*)hi;
        *(uint4*)(outlo + (size_t)node * 256 + lane * 8) = *(const uint4*)lo;
    } else {
        float4* op = (float4*)(outf + (size_t)node * 256 + lane * 8);
        op[0] = make_float4(r[0], r[1], r[2], r[3]);
        op[1] = make_float4(r[4], r[5], r[6], r[7]);
    }
}

// ---- fused softmax + aggregate, H=1, D=16 (ebuf-free) ----------------------
__global__ void __launch_bounds__(256) gat_fused1(
    const int* __restrict__ rp, const int* __restrict__ cs,
    const float* __restrict__ el, const float* __restrict__ er,
    const float* __restrict__ feat, const float* __restrict__ bias,
    float* __restrict__ out)
{
    int warp = (blockIdx.x * blockDim.x + threadIdx.x) >> 5;
    int lane = threadIdx.x & 31;
    if (warp >= NN) return;
    int s0 = rp[warp], s1 = rp[warp + 1];
    float erv = er[warp];

    float t = 0.f;
    for (int i = s0 + lane; i < s1; i += 32) {
        float x = el[cs[i]] + erv;
        x = x > 0.f ? x : 0.2f * x;
        t += __expf(x);
    }
#pragma unroll
    for (int o = 16; o; o >>= 1) t += __shfl_xor_sync(0xffffffffu, t, o);
    float inv = 1.f / t;

    int half = lane >> 4, dk = lane & 15;
    float acc = 0.f;
    for (int i = s0 + half; i < s1; i += 2) {
        int sn = cs[i];
        float x = el[sn] + erv;
        x = x > 0.f ? x : 0.2f * x;
        float a = __expf(x) * inv;
        acc += a * feat[(size_t)sn * 16 + dk];
    }
    acc += __shfl_xor_sync(0xffffffffu, acc, 16);
    if (lane < 16) out[(size_t)warp * 16 + lane] = acc + bias[lane];
}

// ---------------------------------------------------------------------------
extern "C" void kernel_launch(void* const* d_in, const int* in_sizes, int n_in,
                              void* d_out, int out_size) {
    const float* inputs = (const float*)d_in[0];
    const float* W0 = (const float*)d_in[1];
    const float* al0 = (const float*)d_in[2];
    const float* ar0 = (const float*)d_in[3];
    const float* b0 = (const float*)d_in[4];
    const float* W1 = (const float*)d_in[5];
    const float* al1 = (const float*)d_in[6];
    const float* ar1 = (const float*)d_in[7];
    const float* b1 = (const float*)d_in[8];
    const float* W2 = (const float*)d_in[9];
    const float* al2 = (const float*)d_in[10];
    const float* ar2 = (const float*)d_in[11];
    const float* b2 = (const float*)d_in[12];
    const int* src = (const int*)d_in[13];
    const int* dst = (const int*)d_in[14];

    float *feat, *h, *elA, *erA, *elB, *erB;
    int *cnt, *rpp, *cur, *csrc, *bsum;
    __nv_bfloat16 *Ahi, *Alo, *Whi, *Wlo, *Whi2, *Wlo2;
    cudaGetSymbolAddress((void**)&feat, g_feat);
    cudaGetSymbolAddress((void**)&h, g_h);
    cudaGetSymbolAddress((void**)&elA, g_el);
    cudaGetSymbolAddress((void**)&erA, g_er);
    cudaGetSymbolAddress((void**)&elB, g_el2);
    cudaGetSymbolAddress((void**)&erB, g_er2);
    cudaGetSymbolAddress((void**)&cnt, g_cnt);
    cudaGetSymbolAddress((void**)&rpp, g_rp);
    cudaGetSymbolAddress((void**)&cur, g_cur);
    cudaGetSymbolAddress((void**)&csrc, g_csrc);
    cudaGetSymbolAddress((void**)&bsum, g_bsum);
    cudaGetSymbolAddress((void**)&Ahi, g_Ahi);
    cudaGetSymbolAddress((void**)&Alo, g_Alo);
    cudaGetSymbolAddress((void**)&Whi, g_Whi);
    cudaGetSymbolAddress((void**)&Wlo, g_Wlo);
    cudaGetSymbolAddress((void**)&Whi2, g_Whi2);
    cudaGetSymbolAddress((void**)&Wlo2, g_Wlo2);

    cudaFuncSetAttribute(hmma_gemm, cudaFuncAttributeMaxDynamicSharedMemorySize, HMMA_SMEM);

    int warpBlocks = (NN * 32 + 255) / 256;
    dim3 mmaGrid(2, (NN + 127) / 128);

    cudaStream_t sB;
    cudaEvent_t evFork, evCSR, evW1;
    cudaStreamCreateWithFlags(&sB, cudaStreamNonBlocking);
    cudaEventCreateWithFlags(&evFork, cudaEventDisableTiming);
    cudaEventCreateWithFlags(&evCSR, cudaEventDisableTiming);
    cudaEventCreateWithFlags(&evW1, cudaEventDisableTiming);

    cudaEventRecord(evFork, 0);
    cudaStreamWaitEvent(sB, evFork, 0);

    // ---- side stream: CSR build, then convW for layer 1 --------------------
    init_cnt<<<(NN + 255) / 256, 256, 0, sB>>>(cnt);
    hist_kernel<<<(NE + 255) / 256, 256, 0, sB>>>(dst, cnt);
    scan_p1<<<SCAN_BLOCKS, 256, 0, sB>>>(cnt, bsum);
    scan_p2<<<1, 256, 0, sB>>>(bsum);
    scan_p3<<<SCAN_BLOCKS, 32, 0, sB>>>(cnt, bsum, rpp, cur);
    scatter_kernel<<<(NE + 255) / 256, 256, 0, sB>>>(src, dst, cur, csrc);
    cudaEventRecord(evCSR, sB);
    convW_kernel<<<(256 * 256 + 255) / 256, 256, 0, sB>>>(W1, Whi2, Wlo2, 256, elB, erB);
    cudaEventRecord(evW1, sB);

    // ---- main: layer-0 dense path (merged conv kernel) ---------------------
    convAW_kernel<<<(NN * 128 / 4 + 255) / 256, 256>>>(inputs, Ahi, Alo, NN * 128 / 4,
                                                       W0, Whi, Wlo, 128, elA, erA);
    hmma_gemm<<<mmaGrid, 256, HMMA_SMEM>>>(Ahi, Alo, Whi, Wlo, feat, NN, 128,
                                           al0, ar0, elA, erA);
    cudaStreamWaitEvent(0, evCSR, 0);
    gat_fused4<1><<<warpBlocks, 256>>>(rpp, csrc, elA, erA, feat, b0,
                                       nullptr, Ahi, Alo);

    // ---- layer 1 ------------------------------------------------------------
    cudaStreamWaitEvent(0, evW1, 0);
    hmma_gemm<<<mmaGrid, 256, HMMA_SMEM>>>(Ahi, Alo, Whi2, Wlo2, feat, NN, 256,
                                           al1, ar1, elB, erB);
    gat_fused4<0><<<warpBlocks, 256>>>(rpp, csrc, elB, erB, feat, b1,
                                       h, nullptr, nullptr);

    // ---- layer 2 ------------------------------------------------------------
    float* out = (float*)d_out;
    gemm16<<<(NN + 15) / 16, 256>>>(h, W2, feat, NN, al2, ar2, elA, erA);
    gat_fused1<<<warpBlocks, 256>>>(rpp, csrc, elA, erA, feat, b2, out);

    cudaEventDestroy(evFork);
    cudaEventDestroy(evCSR);
    cudaEventDestroy(evW1);
    cudaStreamDestroy(sB);
}

// round 16
// speedup vs baseline: 1.0298x; 1.0298x over previous
#include <cuda_runtime.h>
#include <cuda_bf16.h>
#include <cstdint>

#define NN 50000
#define NE 800000
#define SCAN_BLOCKS 196
#define SCAN_CHUNK  ((NN + SCAN_BLOCKS - 1) / SCAN_BLOCKS)   // 256

// ------------------------- scratch (device globals) -------------------------
__device__ float    g_feat[NN * 256];
__device__ float    g_h[NN * 256];
__device__ float    g_el[NN * 4];
__device__ float    g_er[NN * 4];
__device__ float    g_el2[NN * 4];
__device__ float    g_er2[NN * 4];
__device__ int      g_cnt[NN];
__device__ int      g_rp[NN + 1];
__device__ int      g_cur[NN];
__device__ int      g_csrc[NE];
__device__ int      g_bsum[SCAN_BLOCKS];
__device__ __nv_bfloat16 g_Ahi[NN * 256];
__device__ __nv_bfloat16 g_Alo[NN * 256];
__device__ __nv_bfloat16 g_Whi[256 * 256];
__device__ __nv_bfloat16 g_Wlo[256 * 256];
__device__ __nv_bfloat16 g_Whi2[256 * 256];
__device__ __nv_bfloat16 g_Wlo2[256 * 256];

__device__ __forceinline__ uint32_t smem_u32(const void* p) {
    uint32_t a;
    asm("{ .reg .u64 t; cvta.to.shared.u64 t, %1; cvt.u32.u64 %0, t; }" : "=r"(a) : "l"(p));
    return a;
}
__device__ __forceinline__ void cpa16(uint32_t s, const void* g) {
    asm volatile("cp.async.cg.shared.global [%0], [%1], 16;"
                 :: "r"(s), "l"(__cvta_generic_to_global(g)));
}

// ------------------------- CSR build ----------------------------------------
__global__ void init_cnt(int* __restrict__ cnt) {
    int i = blockIdx.x * blockDim.x + threadIdx.x;
    if (i < NN) cnt[i] = 0;
}
__global__ void hist_kernel(const int* __restrict__ dst, int* __restrict__ cnt) {
    int i = blockIdx.x * blockDim.x + threadIdx.x;
    if (i < NE) atomicAdd(&cnt[dst[i]], 1);
}
__global__ void scan_p1(const int* __restrict__ cnt, int* __restrict__ bsum) {
    __shared__ int red[256];
    int b = blockIdx.x, t = threadIdx.x;
    int beg = b * SCAN_CHUNK;
    int end = beg + SCAN_CHUNK; if (end > NN) end = NN;
    int s = 0;
    for (int i = beg + t; i < end; i += 256) s += cnt[i];
    red[t] = s;
    __syncthreads();
    for (int d = 128; d; d >>= 1) {
        if (t < d) red[t] += red[t + d];
        __syncthreads();
    }
    if (t == 0) bsum[b] = red[0];
}
__global__ void scan_p2(int* __restrict__ bsum) {
    __shared__ int v[256];
    int t = threadIdx.x;
    v[t] = (t < SCAN_BLOCKS) ? bsum[t] : 0;
    __syncthreads();
#pragma unroll
    for (int d = 1; d < 256; d <<= 1) {
        int x = (t >= d) ? v[t - d] : 0;
        __syncthreads();
        v[t] += x;
        __syncthreads();
    }
    if (t < SCAN_BLOCKS) bsum[t] = (t > 0) ? v[t - 1] : 0;
}
__global__ void scan_p3(const int* __restrict__ cnt, const int* __restrict__ bsum,
                        int* __restrict__ rp, int* __restrict__ cur) {
    int b = blockIdx.x, t = threadIdx.x;
    if (t != 0) return;
    int beg = b * SCAN_CHUNK;
    int end = beg + SCAN_CHUNK; if (end > NN) end = NN;
    int off = bsum[b];
    for (int i = beg; i < end; i++) { rp[i] = off; cur[i] = off; off += cnt[i]; }
    if (b == SCAN_BLOCKS - 1) rp[NN] = NE;
}
__global__ void scatter_kernel(const int* __restrict__ src, const int* __restrict__ dst,
                               int* __restrict__ cur, int* __restrict__ csrc) {
    int i = blockIdx.x * blockDim.x + threadIdx.x;
    if (i >= NE) return;
    int p = atomicAdd(&cur[dst[i]], 1);
    csrc[p] = src[i];
}

// ---- merged: convA (layer-0 inputs) + convW (W0) + zero el/er --------------
__global__ void convAW_kernel(const float* __restrict__ A, __nv_bfloat16* __restrict__ Ahi,
                              __nv_bfloat16* __restrict__ Alo, int count4,
                              const float* __restrict__ W, __nv_bfloat16* __restrict__ thi,
                              __nv_bfloat16* __restrict__ tlo, int kin,
                              float* __restrict__ el, float* __restrict__ er) {
    int i = blockIdx.x * blockDim.x + threadIdx.x;
    int gs = gridDim.x * blockDim.x;
    for (int j = i; j < NN * 4; j += gs) { el[j] = 0.f; er[j] = 0.f; }
    for (int j = i; j < kin * 256; j += gs) {
        int k = j >> 8, o = j & 255;
        float v = W[j];
        __nv_bfloat16 hh = __float2bfloat16(v);
        thi[o * kin + k] = hh;
        tlo[o * kin + k] = __float2bfloat16(v - __bfloat162float(hh));
    }
    if (i >= count4) return;
    float4 v = ((const float4*)A)[i];
    __nv_bfloat16 h0 = __float2bfloat16(v.x), h1 = __float2bfloat16(v.y);
    __nv_bfloat16 h2 = __float2bfloat16(v.z), h3 = __float2bfloat16(v.w);
    __nv_bfloat16 l0 = __float2bfloat16(v.x - __bfloat162float(h0));
    __nv_bfloat16 l1 = __float2bfloat16(v.y - __bfloat162float(h1));
    __nv_bfloat16 l2 = __float2bfloat16(v.z - __bfloat162float(h2));
    __nv_bfloat16 l3 = __float2bfloat16(v.w - __bfloat162float(h3));
    __nv_bfloat162* ph = (__nv_bfloat162*)Ahi;
    __nv_bfloat162* pl = (__nv_bfloat162*)Alo;
    ph[i * 2 + 0] = __nv_bfloat162(h0, h1);
    ph[i * 2 + 1] = __nv_bfloat162(h2, h3);
    pl[i * 2 + 0] = __nv_bfloat162(l0, l1);
    pl[i * 2 + 1] = __nv_bfloat162(l2, l3);
}

__global__ void convW_kernel(const float* __restrict__ W, __nv_bfloat16* __restrict__ thi,
                             __nv_bfloat16* __restrict__ tlo, int kin,
                             float* __restrict__ el, float* __restrict__ er) {
    int i = blockIdx.x * blockDim.x + threadIdx.x;
    for (int j = i; j < NN * 4; j += gridDim.x * blockDim.x) { el[j] = 0.f; er[j] = 0.f; }
    if (i >= kin * 256) return;
    int k = i >> 8, o = i & 255;
    float v = W[i];
    __nv_bfloat16 h = __float2bfloat16(v);
    thi[o * kin + k] = h;
    tlo[o * kin + k] = __float2bfloat16(v - __bfloat162float(h));
}

// ------- HMMA GEMM, cp.async double-buffered, fused el/er epilogue ----------
#define HMMA_STAGE 65536
#define HMMA_SMEM  (2 * HMMA_STAGE)

__device__ __forceinline__ void mma16816(float* c, const uint32_t* a, const uint32_t* b) {
    asm volatile(
        "mma.sync.aligned.m16n8k16.row.col.f32.bf16.bf16.f32 "
        "{%0,%1,%2,%3}, {%4,%5,%6,%7}, {%8,%9}, {%0,%1,%2,%3};"
        : "+f"(c[0]), "+f"(c[1]), "+f"(c[2]), "+f"(c[3])
        : "r"(a[0]), "r"(a[1]), "r"(a[2]), "r"(a[3]), "r"(b[0]), "r"(b[1]));
}
__device__ __forceinline__ void ldsm4(uint32_t* r, uint32_t addr) {
    asm volatile("ldmatrix.sync.aligned.m8n8.x4.shared.b16 {%0,%1,%2,%3}, [%4];"
                 : "=r"(r[0]), "=r"(r[1]), "=r"(r[2]), "=r"(r[3]) : "r"(addr));
}

__global__ void __launch_bounds__(256, 1) hmma_gemm(
    const __nv_bfloat16* __restrict__ Ahi, const __nv_bfloat16* __restrict__ Alo,
    const __nv_bfloat16* __restrict__ Bhi, const __nv_bfloat16* __restrict__ Blo,
    float* __restrict__ C, int n, int kin,
    const float* __restrict__ alv, const float* __restrict__ arv,
    float* __restrict__ elo, float* __restrict__ ero)
{
    extern __shared__ char smem[];
    int tid = threadIdx.x, wid = tid >> 5, lane = tid & 31;
    int baseM = blockIdx.y * 128;
    int baseN = blockIdx.x * 128;
    int wm = wid >> 2, wn = wid & 3;

    float acc[4][4][4];
#pragma unroll
    for (int i = 0; i < 4; i++)
#pragma unroll
        for (int j = 0; j < 4; j++)
#pragma unroll
            for (int q = 0; q < 4; q++) acc[i][j][q] = 0.f;

    int arow = wm * 64 + (lane & 15);
    int ahalf16 = (lane >> 4) * 16;
    int brow = wn * 32 + ((lane >> 4) << 3) + (lane & 7);
    int bhalf16 = ((lane >> 3) & 1) * 16;

    uint32_t sb = smem_u32(smem);
    int nchunks = kin >> 6;

    auto load_chunk = [&](int kc, int stg) {
        uint32_t base = sb + stg * HMMA_STAGE;
#pragma unroll
        for (int it = 0; it < 4; it++) {
            int c = it * 256 + tid;
            int row = c >> 3, cj = c & 7;
            uint32_t off = row * 128 + ((cj * 16) ^ ((row & 7) << 4));
            int gr = baseM + row;
            if (gr < n) {
                size_t gi = (size_t)gr * kin + kc * 64 + cj * 8;
                cpa16(base + off, Ahi + gi);
                cpa16(base + 16384 + off, Alo + gi);
            } else {
                *(uint4*)(smem + stg * HMMA_STAGE + off) = make_uint4(0, 0, 0, 0);
                *(uint4*)(smem + stg * HMMA_STAGE + 16384 + off) = make_uint4(0, 0, 0, 0);
            }
            size_t wi = (size_t)(baseN + row) * kin + kc * 64 + cj * 8;
            cpa16(base + 32768 + off, Bhi + wi);
            cpa16(base + 49152 + off, Blo + wi);
        }
        asm volatile("cp.async.commit_group;" ::: "memory");
    };

    load_chunk(0, 0);
    for (int kc = 0; kc < nchunks; kc++) {
        if (kc + 1 < nchunks) {
            load_chunk(kc + 1, (kc + 1) & 1);
            asm volatile("cp.async.wait_group 1;" ::: "memory");
        } else {
            asm volatile("cp.async.wait_group 0;" ::: "memory");
        }
        __syncthreads();

        uint32_t sA  = sb + (kc & 1) * HMMA_STAGE;
        uint32_t sAl = sA + 16384;
        uint32_t sW  = sA + 32768;
        uint32_t sWl = sA + 49152;
#pragma unroll
        for (int s = 0; s < 4; s++) {
            uint32_t ah[4][4], al_[4][4], bh[2][4], bl[2][4];
#pragma unroll
            for (int mi = 0; mi < 4; mi++) {
                int r = arow + mi * 16;
                uint32_t off = r * 128 + ((s * 32 + ahalf16) ^ ((r & 7) << 4));
                ldsm4(ah[mi], sA + off);
                ldsm4(al_[mi], sAl + off);
            }
#pragma unroll
            for (int p = 0; p < 2; p++) {
                int r = brow + p * 16;
                uint32_t off = r * 128 + ((s * 32 + bhalf16) ^ ((r & 7) << 4));
                ldsm4(bh[p], sW + off);
                ldsm4(bl[p], sWl + off);
            }
#pragma unroll
            for (int mi = 0; mi < 4; mi++)
#pragma unroll
                for (int p = 0; p < 2; p++)
#pragma unroll
                    for (int q = 0; q < 2; q++) {
                        int t = p * 2 + q;
                        mma16816(acc[mi][t], ah[mi], &bh[p][q * 2]);
                        mma16816(acc[mi][t], ah[mi], &bl[p][q * 2]);
                        mma16816(acc[mi][t], al_[mi], &bh[p][q * 2]);
                    }
        }
        __syncthreads();
    }

    int g = lane >> 2, t4 = lane & 3;

#pragma unroll
    for (int mi = 0; mi < 4; mi++) {
        int r0 = baseM + wm * 64 + mi * 16 + g;
        int r1 = r0 + 8;
#pragma unroll
        for (int t = 0; t < 4; t++) {
            int col = baseN + wn * 32 + t * 8 + t4 * 2;
            if (r0 < n) *(float2*)(C + (size_t)r0 * 256 + col) = make_float2(acc[mi][t][0], acc[mi][t][1]);
            if (r1 < n) *(float2*)(C + (size_t)r1 * 256 + col) = make_float2(acc[mi][t][2], acc[mi][t][3]);
        }
    }

    int hh = (baseN + wn * 32) >> 6;
    float av[4][2], rv[4][2];
#pragma unroll
    for (int t = 0; t < 4; t++) {
        int col = baseN + wn * 32 + t * 8 + t4 * 2;
        av[t][0] = alv[col]; av[t][1] = alv[col + 1];
        rv[t][0] = arv[col]; rv[t][1] = arv[col + 1];
    }
#pragma unroll
    for (int mi = 0; mi < 4; mi++) {
        float e0 = 0.f, e1 = 0.f, f0 = 0.f, f1 = 0.f;
#pragma unroll
        for (int t = 0; t < 4; t++) {
            e0 += acc[mi][t][0] * av[t][0] + acc[mi][t][1] * av[t][1];
            e1 += acc[mi][t][2] * av[t][0] + acc[mi][t][3] * av[t][1];
            f0 += acc[mi][t][0] * rv[t][0] + acc[mi][t][1] * rv[t][1];
            f1 += acc[mi][t][2] * rv[t][0] + acc[mi][t][3] * rv[t][1];
        }
#pragma unroll
        for (int o = 1; o <= 2; o <<= 1) {
            e0 += __shfl_xor_sync(0xffffffffu, e0, o);
            e1 += __shfl_xor_sync(0xffffffffu, e1, o);
            f0 += __shfl_xor_sync(0xffffffffu, f0, o);
            f1 += __shfl_xor_sync(0xffffffffu, f1, o);
        }
        if (t4 == 0) {
            int r0 = baseM + wm * 64 + mi * 16 + g;
            int r1 = r0 + 8;
            if (r0 < n) { atomicAdd(&elo[r0 * 4 + hh], e0); atomicAdd(&ero[r0 * 4 + hh], f0); }
            if (r1 < n) { atomicAdd(&elo[r1 * 4 + hh], e1); atomicAdd(&ero[r1 * 4 + hh], f1); }
        }
    }
}

// --------- small GEMM for layer 2 (kin=256, kout=16) + fused el/er ----------
// 32 rows per block (512 threads): halves block count and W2 reload traffic.
__global__ void __launch_bounds__(512) gemm16(
    const float* __restrict__ A, const float* __restrict__ W,
    float* __restrict__ C, int n,
    const float* __restrict__ alv, const float* __restrict__ arv,
    float* __restrict__ elo, float* __restrict__ ero) {
    __shared__ float As[32][256];
    __shared__ float Wt[16][260];
    int tid = threadIdx.x;
    int base = blockIdx.x * 32;
    for (int i = tid; i < 4096; i += 512) {
        int k = i >> 4, oi = i & 15;
        Wt[oi][k] = W[i];
    }
    for (int i = tid; i < 2048; i += 512) {
        int r = i >> 6, c4 = i & 63;
        float4 v = make_float4(0.f, 0.f, 0.f, 0.f);
        if (base + r < n) v = ((const float4*)(A + (size_t)(base + r) * 256))[c4];
        ((float4*)&As[r][0])[c4] = v;
    }
    __syncthreads();
    int ni = tid >> 4, oi = tid & 15;
    float acc = 0.f;
#pragma unroll 16
    for (int k4 = 0; k4 < 64; k4++) {
        float4 a = ((const float4*)&As[ni][0])[k4];
        float4 w = *(const float4*)&Wt[oi][k4 * 4];
        acc += a.x * w.x + a.y * w.y + a.z * w.z + a.w * w.w;
    }
    if (base + ni < n) C[(size_t)(base + ni) * 16 + oi] = acc;

    float e = acc * alv[oi], f = acc * arv[oi];
#pragma unroll
    for (int o = 8; o; o >>= 1) {
        e += __shfl_xor_sync(0xffffffffu, e, o);
        f += __shfl_xor_sync(0xffffffffu, f, o);
    }
    if (oi == 0 && base + ni < n) { elo[base + ni] = e; ero[base + ni] = f; }
}

// ---- fused softmax + aggregate, H=4, D=64 (ebuf-free, unroll x2: FINAL) ----
template <int OUT_BF16>
__global__ void __launch_bounds__(256) gat_fused4(
    const int* __restrict__ rp, const int* __restrict__ cs,
    const float* __restrict__ el, const float* __restrict__ er,
    const float* __restrict__ feat, const float* __restrict__ bias,
    float* __restrict__ outf,
    __nv_bfloat16* __restrict__ outhi, __nv_bfloat16* __restrict__ outlo)
{
    int node = (blockIdx.x * blockDim.x + threadIdx.x) >> 5;
    int lane = threadIdx.x & 31;
    if (node >= NN) return;
    int s0 = rp[node], s1 = rp[node + 1];

    float4 er4 = *(const float4*)&er[node * 4];

    // pass A: sum of exp(leaky(logit)) per head
    float t0 = 0.f, t1 = 0.f, t2 = 0.f, t3 = 0.f;
    for (int i = s0 + lane; i < s1; i += 32) {
        int sn = cs[i];
        float4 lv = *(const float4*)&el[sn * 4];
        lv.x += er4.x; lv.y += er4.y; lv.z += er4.z; lv.w += er4.w;
        lv.x = lv.x > 0.f ? lv.x : 0.2f * lv.x;
        lv.y = lv.y > 0.f ? lv.y : 0.2f * lv.y;
        lv.z = lv.z > 0.f ? lv.z : 0.2f * lv.z;
        lv.w = lv.w > 0.f ? lv.w : 0.2f * lv.w;
        t0 += __expf(lv.x); t1 += __expf(lv.y);
        t2 += __expf(lv.z); t3 += __expf(lv.w);
    }
#pragma unroll
    for (int o = 16; o; o >>= 1) {
        t0 += __shfl_xor_sync(0xffffffffu, t0, o);
        t1 += __shfl_xor_sync(0xffffffffu, t1, o);
        t2 += __shfl_xor_sync(0xffffffffu, t2, o);
        t3 += __shfl_xor_sync(0xffffffffu, t3, o);
    }

    int hl = lane >> 3;
    float sv = hl == 0 ? t0 : hl == 1 ? t1 : hl == 2 ? t2 : t3;
    float erh = hl == 0 ? er4.x : hl == 1 ? er4.y : hl == 2 ? er4.z : er4.w;
    float inv = 1.f / sv;

    // pass C: recompute alpha + gather (unroll x2)
    float a0 = 0.f, a1 = 0.f, a2 = 0.f, a3 = 0.f, a4 = 0.f, a5 = 0.f, a6 = 0.f, a7 = 0.f;
    int i = s0;
    for (; i + 2 <= s1; i += 2) {
        int sn0 = cs[i], sn1 = cs[i + 1];
        float x0 = el[sn0 * 4 + hl] + erh;
        float x1 = el[sn1 * 4 + hl] + erh;
        x0 = x0 > 0.f ? x0 : 0.2f * x0;
        x1 = x1 > 0.f ? x1 : 0.2f * x1;
        float aa0 = __expf(x0) * inv;
        float aa1 = __expf(x1) * inv;
        const float4* fp0 = (const float4*)(feat + (size_t)sn0 * 256 + lane * 8);
        const float4* fp1 = (const float4*)(feat + (size_t)sn1 * 256 + lane * 8);
        float4 u0 = fp0[0], u1 = fp0[1];
        float4 w0 = fp1[0], w1 = fp1[1];
        a0 += aa0 * u0.x + aa1 * w0.x; a1 += aa0 * u0.y + aa1 * w0.y;
        a2 += aa0 * u0.z + aa1 * w0.z; a3 += aa0 * u0.w + aa1 * w0.w;
        a4 += aa0 * u1.x + aa1 * w1.x; a5 += aa0 * u1.y + aa1 * w1.y;
        a6 += aa0 * u1.z + aa1 * w1.z; a7 += aa0 * u1.w + aa1 * w1.w;
    }
    if (i < s1) {
        int sn = cs[i];
        float x = el[sn * 4 + hl] + erh;
        x = x > 0.f ? x : 0.2f * x;
        float a = __expf(x) * inv;
        const float4* fp = (const float4*)(feat + (size_t)sn * 256 + lane * 8);
        float4 v0 = fp[0], v1 = fp[1];
        a0 += a * v0.x; a1 += a * v0.y; a2 += a * v0.z; a3 += a * v0.w;
        a4 += a * v1.x; a5 += a * v1.y; a6 += a * v1.z; a7 += a * v1.w;
    }
    const float4* bp = (const float4*)(bias + lane * 8);
    float4 b0 = bp[0], b1 = bp[1];
    float r[8] = { a0 + b0.x, a1 + b0.y, a2 + b0.z, a3 + b0.w,
                   a4 + b1.x, a5 + b1.y, a6 + b1.z, a7 + b1.w };
    if (OUT_BF16) {
        __nv_bfloat16 hi[8], lo[8];
#pragma unroll
        for (int q = 0; q < 8; q++) {
            hi[q] = __float2bfloat16(r[q]);
            lo[q] = __float2bfloat16(r[q] - __bfloat162float(hi[q]));
        }
        *(uint4*)(outhi + (size_t)node * 256 + lane * 8) = *(const uint4*)hi;
        *(uint4*)(outlo + (size_t)node * 256 + lane * 8) = *(const uint4*)lo;
    } else {
        float4* op = (float4*)(outf + (size_t)node * 256 + lane * 8);
        op[0] = make_float4(r[0], r[1], r[2], r[3]);
        op[1] = make_float4(r[4], r[5], r[6], r[7]);
    }
}

// ---- fused softmax + aggregate, H=1, D=16 (ebuf-free) ----------------------
__global__ void __launch_bounds__(256) gat_fused1(
    const int* __restrict__ rp, const int* __restrict__ cs,
    const float* __restrict__ el, const float* __restrict__ er,
    const float* __restrict__ feat, const float* __restrict__ bias,
    float* __restrict__ out)
{
    int warp = (blockIdx.x * blockDim.x + threadIdx.x) >> 5;
    int lane = threadIdx.x & 31;
    if (warp >= NN) return;
    int s0 = rp[warp], s1 = rp[warp + 1];
    float erv = er[warp];

    float t = 0.f;
    for (int i = s0 + lane; i < s1; i += 32) {
        float x = el[cs[i]] + erv;
        x = x > 0.f ? x : 0.2f * x;
        t += __expf(x);
    }
#pragma unroll
    for (int o = 16; o; o >>= 1) t += __shfl_xor_sync(0xffffffffu, t, o);
    float inv = 1.f / t;

    int half = lane >> 4, dk = lane & 15;
    float acc = 0.f;
    for (int i = s0 + half; i < s1; i += 2) {
        int sn = cs[i];
        float x = el[sn] + erv;
        x = x > 0.f ? x : 0.2f * x;
        float a = __expf(x) * inv;
        acc += a * feat[(size_t)sn * 16 + dk];
    }
    acc += __shfl_xor_sync(0xffffffffu, acc, 16);
    if (lane < 16) out[(size_t)warp * 16 + lane] = acc + bias[lane];
}

// ---------------------------------------------------------------------------
extern "C" void kernel_launch(void* const* d_in, const int* in_sizes, int n_in,
                              void* d_out, int out_size) {
    const float* inputs = (const float*)d_in[0];
    const float* W0 = (const float*)d_in[1];
    const float* al0 = (const float*)d_in[2];
    const float* ar0 = (const float*)d_in[3];
    const float* b0 = (const float*)d_in[4];
    const float* W1 = (const float*)d_in[5];
    const float* al1 = (const float*)d_in[6];
    const float* ar1 = (const float*)d_in[7];
    const float* b1 = (const float*)d_in[8];
    const float* W2 = (const float*)d_in[9];
    const float* al2 = (const float*)d_in[10];
    const float* ar2 = (const float*)d_in[11];
    const float* b2 = (const float*)d_in[12];
    const int* src = (const int*)d_in[13];
    const int* dst = (const int*)d_in[14];

    float *feat, *h, *elA, *erA, *elB, *erB;
    int *cnt, *rpp, *cur, *csrc, *bsum;
    __nv_bfloat16 *Ahi, *Alo, *Whi, *Wlo, *Whi2, *Wlo2;
    cudaGetSymbolAddress((void**)&feat, g_feat);
    cudaGetSymbolAddress((void**)&h, g_h);
    cudaGetSymbolAddress((void**)&elA, g_el);
    cudaGetSymbolAddress((void**)&erA, g_er);
    cudaGetSymbolAddress((void**)&elB, g_el2);
    cudaGetSymbolAddress((void**)&erB, g_er2);
    cudaGetSymbolAddress((void**)&cnt, g_cnt);
    cudaGetSymbolAddress((void**)&rpp, g_rp);
    cudaGetSymbolAddress((void**)&cur, g_cur);
    cudaGetSymbolAddress((void**)&csrc, g_csrc);
    cudaGetSymbolAddress((void**)&bsum, g_bsum);
    cudaGetSymbolAddress((void**)&Ahi, g_Ahi);
    cudaGetSymbolAddress((void**)&Alo, g_Alo);
    cudaGetSymbolAddress((void**)&Whi, g_Whi);
    cudaGetSymbolAddress((void**)&Wlo, g_Wlo);
    cudaGetSymbolAddress((void**)&Whi2, g_Whi2);
    cudaGetSymbolAddress((void**)&Wlo2, g_Wlo2);

    cudaFuncSetAttribute(hmma_gemm, cudaFuncAttributeMaxDynamicSharedMemorySize, HMMA_SMEM);

    int warpBlocks = (NN * 32 + 255) / 256;
    dim3 mmaGrid(2, (NN + 127) / 128);

    cudaStream_t sB;
    cudaEvent_t evFork, evCSR, evW1;
    cudaStreamCreateWithFlags(&sB, cudaStreamNonBlocking);
    cudaEventCreateWithFlags(&evFork, cudaEventDisableTiming);
    cudaEventCreateWithFlags(&evCSR, cudaEventDisableTiming);
    cudaEventCreateWithFlags(&evW1, cudaEventDisableTiming);

    cudaEventRecord(evFork, 0);
    cudaStreamWaitEvent(sB, evFork, 0);

    // ---- side stream: CSR build, then convW for layer 1 --------------------
    init_cnt<<<(NN + 255) / 256, 256, 0, sB>>>(cnt);
    hist_kernel<<<(NE + 255) / 256, 256, 0, sB>>>(dst, cnt);
    scan_p1<<<SCAN_BLOCKS, 256, 0, sB>>>(cnt, bsum);
    scan_p2<<<1, 256, 0, sB>>>(bsum);
    scan_p3<<<SCAN_BLOCKS, 32, 0, sB>>>(cnt, bsum, rpp, cur);
    scatter_kernel<<<(NE + 255) / 256, 256, 0, sB>>>(src, dst, cur, csrc);
    cudaEventRecord(evCSR, sB);
    convW_kernel<<<(256 * 256 + 255) / 256, 256, 0, sB>>>(W1, Whi2, Wlo2, 256, elB, erB);
    cudaEventRecord(evW1, sB);

    // ---- main: layer-0 dense path (merged conv kernel) ---------------------
    convAW_kernel<<<(NN * 128 / 4 + 255) / 256, 256>>>(inputs, Ahi, Alo, NN * 128 / 4,
                                                       W0, Whi, Wlo, 128, elA, erA);
    hmma_gemm<<<mmaGrid, 256, HMMA_SMEM>>>(Ahi, Alo, Whi, Wlo, feat, NN, 128,
                                           al0, ar0, elA, erA);
    cudaStreamWaitEvent(0, evCSR, 0);
    gat_fused4<1><<<warpBlocks, 256>>>(rpp, csrc, elA, erA, feat, b0,
                                       nullptr, Ahi, Alo);

    // ---- layer 1 ------------------------------------------------------------
    cudaStreamWaitEvent(0, evW1, 0);
    hmma_gemm<<<mmaGrid, 256, HMMA_SMEM>>>(Ahi, Alo, Whi2, Wlo2, feat, NN, 256,
                                           al1, ar1, elB, erB);
    gat_fused4<0><<<warpBlocks, 256>>>(rpp, csrc, elB, erB, feat, b1,
                                       h, nullptr, nullptr);

    // ---- layer 2 ------------------------------------------------------------
    float* out = (float*)d_out;
    gemm16<<<(NN + 31) / 32, 512>>>(h, W2, feat, NN, al2, ar2, elA, erA);
    gat_fused1<<<warpBlocks, 256>>>(rpp, csrc, elA, erA, feat, b2, out);

    cudaEventDestroy(evFork);
    cudaEventDestroy(evCSR);
    cudaEventDestroy(evW1);
    cudaStreamDestroy(sB);
}

// round 17
// speedup vs baseline: 1.0589x; 1.0282x over previous
#include <cuda_runtime.h>
#include <cuda_bf16.h>
#include <cstdint>

#define NN 50000
#define NE 800000
#define SCAN_BLOCKS 196
#define SCAN_CHUNK  ((NN + SCAN_BLOCKS - 1) / SCAN_BLOCKS)   // 256

// ------------------------- scratch (device globals) -------------------------
__device__ float    g_feat[NN * 256];
__device__ float    g_h[NN * 256];
__device__ float    g_el[NN * 4];
__device__ float    g_er[NN * 4];
__device__ float    g_el2[NN * 4];
__device__ float    g_er2[NN * 4];
__device__ int      g_cnt[NN];
__device__ int      g_rp[NN + 1];
__device__ int      g_cur[NN];
__device__ int      g_csrc[NE];
__device__ int      g_bsum[SCAN_BLOCKS];
__device__ __nv_bfloat16 g_Ahi[NN * 256];
__device__ __nv_bfloat16 g_Alo[NN * 256];
__device__ __nv_bfloat16 g_Whi[256 * 256];
__device__ __nv_bfloat16 g_Wlo[256 * 256];
__device__ __nv_bfloat16 g_Whi2[256 * 256];
__device__ __nv_bfloat16 g_Wlo2[256 * 256];

__device__ __forceinline__ uint32_t smem_u32(const void* p) {
    uint32_t a;
    asm("{ .reg .u64 t; cvta.to.shared.u64 t, %1; cvt.u32.u64 %0, t; }" : "=r"(a) : "l"(p));
    return a;
}
__device__ __forceinline__ void cpa16(uint32_t s, const void* g) {
    asm volatile("cp.async.cg.shared.global [%0], [%1], 16;"
                 :: "r"(s), "l"(__cvta_generic_to_global(g)));
}

// ------------------------- CSR build ----------------------------------------
__global__ void init_cnt(int* __restrict__ cnt) {
    int i = blockIdx.x * blockDim.x + threadIdx.x;
    if (i < NN) cnt[i] = 0;
}
__global__ void hist_kernel(const int* __restrict__ dst, int* __restrict__ cnt) {
    int i = blockIdx.x * blockDim.x + threadIdx.x;
    if (i < NE) atomicAdd(&cnt[dst[i]], 1);
}
__global__ void scan_p1(const int* __restrict__ cnt, int* __restrict__ bsum) {
    __shared__ int red[256];
    int b = blockIdx.x, t = threadIdx.x;
    int beg = b * SCAN_CHUNK;
    int end = beg + SCAN_CHUNK; if (end > NN) end = NN;
    int s = 0;
    for (int i = beg + t; i < end; i += 256) s += cnt[i];
    red[t] = s;
    __syncthreads();
    for (int d = 128; d; d >>= 1) {
        if (t < d) red[t] += red[t + d];
        __syncthreads();
    }
    if (t == 0) bsum[b] = red[0];
}
__global__ void scan_p2(int* __restrict__ bsum) {
    __shared__ int v[256];
    int t = threadIdx.x;
    v[t] = (t < SCAN_BLOCKS) ? bsum[t] : 0;
    __syncthreads();
#pragma unroll
    for (int d = 1; d < 256; d <<= 1) {
        int x = (t >= d) ? v[t - d] : 0;
        __syncthreads();
        v[t] += x;
        __syncthreads();
    }
    if (t < SCAN_BLOCKS) bsum[t] = (t > 0) ? v[t - 1] : 0;
}
__global__ void scan_p3(const int* __restrict__ cnt, const int* __restrict__ bsum,
                        int* __restrict__ rp, int* __restrict__ cur) {
    int b = blockIdx.x, t = threadIdx.x;
    if (t != 0) return;
    int beg = b * SCAN_CHUNK;
    int end = beg + SCAN_CHUNK; if (end > NN) end = NN;
    int off = bsum[b];
    for (int i = beg; i < end; i++) { rp[i] = off; cur[i] = off; off += cnt[i]; }
    if (b == SCAN_BLOCKS - 1) rp[NN] = NE;
}
__global__ void scatter_kernel(const int* __restrict__ src, const int* __restrict__ dst,
                               int* __restrict__ cur, int* __restrict__ csrc) {
    int i = blockIdx.x * blockDim.x + threadIdx.x;
    if (i >= NE) return;
    int p = atomicAdd(&cur[dst[i]], 1);
    csrc[p] = src[i];
}

// ---- merged: convA (layer-0 inputs) + convW (W0) + zero el/er --------------
__global__ void convAW_kernel(const float* __restrict__ A, __nv_bfloat16* __restrict__ Ahi,
                              __nv_bfloat16* __restrict__ Alo, int count4,
                              const float* __restrict__ W, __nv_bfloat16* __restrict__ thi,
                              __nv_bfloat16* __restrict__ tlo, int kin,
                              float* __restrict__ el, float* __restrict__ er) {
    int i = blockIdx.x * blockDim.x + threadIdx.x;
    int gs = gridDim.x * blockDim.x;
    for (int j = i; j < NN * 4; j += gs) { el[j] = 0.f; er[j] = 0.f; }
    for (int j = i; j < kin * 256; j += gs) {
        int k = j >> 8, o = j & 255;
        float v = W[j];
        __nv_bfloat16 hh = __float2bfloat16(v);
        thi[o * kin + k] = hh;
        tlo[o * kin + k] = __float2bfloat16(v - __bfloat162float(hh));
    }
    if (i >= count4) return;
    float4 v = ((const float4*)A)[i];
    __nv_bfloat16 h0 = __float2bfloat16(v.x), h1 = __float2bfloat16(v.y);
    __nv_bfloat16 h2 = __float2bfloat16(v.z), h3 = __float2bfloat16(v.w);
    __nv_bfloat16 l0 = __float2bfloat16(v.x - __bfloat162float(h0));
    __nv_bfloat16 l1 = __float2bfloat16(v.y - __bfloat162float(h1));
    __nv_bfloat16 l2 = __float2bfloat16(v.z - __bfloat162float(h2));
    __nv_bfloat16 l3 = __float2bfloat16(v.w - __bfloat162float(h3));
    __nv_bfloat162* ph = (__nv_bfloat162*)Ahi;
    __nv_bfloat162* pl = (__nv_bfloat162*)Alo;
    ph[i * 2 + 0] = __nv_bfloat162(h0, h1);
    ph[i * 2 + 1] = __nv_bfloat162(h2, h3);
    pl[i * 2 + 0] = __nv_bfloat162(l0, l1);
    pl[i * 2 + 1] = __nv_bfloat162(l2, l3);
}

__global__ void convW_kernel(const float* __restrict__ W, __nv_bfloat16* __restrict__ thi,
                             __nv_bfloat16* __restrict__ tlo, int kin,
                             float* __restrict__ el, float* __restrict__ er) {
    int i = blockIdx.x * blockDim.x + threadIdx.x;
    for (int j = i; j < NN * 4; j += gridDim.x * blockDim.x) { el[j] = 0.f; er[j] = 0.f; }
    if (i >= kin * 256) return;
    int k = i >> 8, o = i & 255;
    float v = W[i];
    __nv_bfloat16 h = __float2bfloat16(v);
    thi[o * kin + k] = h;
    tlo[o * kin + k] = __float2bfloat16(v - __bfloat162float(h));
}

// ------- HMMA GEMM: 128(M) x 256(N) CTA tile, 512 thr, cp.async 2-stage -----
#define HMMA_STAGE 98304                 // A hi/lo 16K+16K, B hi/lo 32K+32K
#define HMMA_SMEM  (2 * HMMA_STAGE)      // 192KB

__device__ __forceinline__ void mma16816(float* c, const uint32_t* a, const uint32_t* b) {
    asm volatile(
        "mma.sync.aligned.m16n8k16.row.col.f32.bf16.bf16.f32 "
        "{%0,%1,%2,%3}, {%4,%5,%6,%7}, {%8,%9}, {%0,%1,%2,%3};"
        : "+f"(c[0]), "+f"(c[1]), "+f"(c[2]), "+f"(c[3])
        : "r"(a[0]), "r"(a[1]), "r"(a[2]), "r"(a[3]), "r"(b[0]), "r"(b[1]));
}
__device__ __forceinline__ void ldsm4(uint32_t* r, uint32_t addr) {
    asm volatile("ldmatrix.sync.aligned.m8n8.x4.shared.b16 {%0,%1,%2,%3}, [%4];"
                 : "=r"(r[0]), "=r"(r[1]), "=r"(r[2]), "=r"(r[3]) : "r"(addr));
}

__global__ void __launch_bounds__(512, 1) hmma_gemm(
    const __nv_bfloat16* __restrict__ Ahi, const __nv_bfloat16* __restrict__ Alo,
    const __nv_bfloat16* __restrict__ Bhi, const __nv_bfloat16* __restrict__ Blo,
    float* __restrict__ C, int n, int kin,
    const float* __restrict__ alv, const float* __restrict__ arv,
    float* __restrict__ elo, float* __restrict__ ero)
{
    extern __shared__ char smem[];
    int tid = threadIdx.x, wid = tid >> 5, lane = tid & 31;
    int baseM = blockIdx.y * 128;
    int wm = wid >> 2, wn = wid & 3;    // warp tile: rows wm*32, cols wn*64

    float acc[2][8][4];
#pragma unroll
    for (int i = 0; i < 2; i++)
#pragma unroll
        for (int j = 0; j < 8; j++)
#pragma unroll
            for (int q = 0; q < 4; q++) acc[i][j][q] = 0.f;

    int arow = wm * 32 + (lane & 15);
    int ahalf16 = (lane >> 4) * 16;
    int brow = wn * 64 + ((lane >> 4) << 3) + (lane & 7);
    int bhalf16 = ((lane >> 3) & 1) * 16;

    uint32_t sb = smem_u32(smem);
    int nchunks = kin >> 6;

    auto load_chunk = [&](int kc, int stg) {
        uint32_t base = sb + stg * HMMA_STAGE;
        // A hi/lo: 128 rows x 8 chunks of 16B
        for (int c = tid; c < 1024; c += 512) {
            int row = c >> 3, cj = c & 7;
            uint32_t off = row * 128 + ((cj * 16) ^ ((row & 7) << 4));
            int gr = baseM + row;
            if (gr < n) {
                size_t gi = (size_t)gr * kin + kc * 64 + cj * 8;
                cpa16(base + off, Ahi + gi);
                cpa16(base + 16384 + off, Alo + gi);
            } else {
                *(uint4*)(smem + stg * HMMA_STAGE + off) = make_uint4(0, 0, 0, 0);
                *(uint4*)(smem + stg * HMMA_STAGE + 16384 + off) = make_uint4(0, 0, 0, 0);
            }
        }
        // B hi/lo: 256 rows x 8 chunks of 16B
        for (int c = tid; c < 2048; c += 512) {
            int row = c >> 3, cj = c & 7;
            uint32_t off = row * 128 + ((cj * 16) ^ ((row & 7) << 4));
            size_t wi = (size_t)row * kin + kc * 64 + cj * 8;
            cpa16(base + 32768 + off, Bhi + wi);
            cpa16(base + 65536 + off, Blo + wi);
        }
        asm volatile("cp.async.commit_group;" ::: "memory");
    };

    load_chunk(0, 0);
    for (int kc = 0; kc < nchunks; kc++) {
        if (kc + 1 < nchunks) {
            load_chunk(kc + 1, (kc + 1) & 1);
            asm volatile("cp.async.wait_group 1;" ::: "memory");
        } else {
            asm volatile("cp.async.wait_group 0;" ::: "memory");
        }
        __syncthreads();

        uint32_t sA  = sb + (kc & 1) * HMMA_STAGE;
        uint32_t sAl = sA + 16384;
        uint32_t sW  = sA + 32768;
        uint32_t sWl = sA + 65536;
#pragma unroll
        for (int s = 0; s < 4; s++) {
            uint32_t ah[2][4], al_[2][4];
#pragma unroll
            for (int mi = 0; mi < 2; mi++) {
                int r = arow + mi * 16;
                uint32_t off = r * 128 + ((s * 32 + ahalf16) ^ ((r & 7) << 4));
                ldsm4(ah[mi], sA + off);
                ldsm4(al_[mi], sAl + off);
            }
            // process the 64 N cols in two 32-col halves (keeps B regs low)
#pragma unroll
            for (int pp = 0; pp < 2; pp++) {
                uint32_t bh[2][4], bl[2][4];
#pragma unroll
                for (int p2 = 0; p2 < 2; p2++) {
                    int r = brow + (pp * 2 + p2) * 16;
                    uint32_t off = r * 128 + ((s * 32 + bhalf16) ^ ((r & 7) << 4));
                    ldsm4(bh[p2], sW + off);
                    ldsm4(bl[p2], sWl + off);
                }
#pragma unroll
                for (int mi = 0; mi < 2; mi++)
#pragma unroll
                    for (int p2 = 0; p2 < 2; p2++)
#pragma unroll
                        for (int q = 0; q < 2; q++) {
                            int t = (pp * 2 + p2) * 2 + q;
                            mma16816(acc[mi][t], ah[mi], &bh[p2][q * 2]);
                            mma16816(acc[mi][t], ah[mi], &bl[p2][q * 2]);
                            mma16816(acc[mi][t], al_[mi], &bh[p2][q * 2]);
                        }
            }
        }
        __syncthreads();
    }

    int g = lane >> 2, t4 = lane & 3;

    // ---- write C ----
#pragma unroll
    for (int mi = 0; mi < 2; mi++) {
        int r0 = baseM + wm * 32 + mi * 16 + g;
        int r1 = r0 + 8;
#pragma unroll
        for (int t = 0; t < 8; t++) {
            int col = wn * 64 + t * 8 + t4 * 2;
            if (r0 < n) *(float2*)(C + (size_t)r0 * 256 + col) = make_float2(acc[mi][t][0], acc[mi][t][1]);
            if (r1 < n) *(float2*)(C + (size_t)r1 * 256 + col) = make_float2(acc[mi][t][2], acc[mi][t][3]);
        }
    }

    // ---- fused el/er epilogue: warp's 64 cols = exactly head wn ----
    int hh = wn;
    float av[8][2], rv[8][2];
#pragma unroll
    for (int t = 0; t < 8; t++) {
        int col = wn * 64 + t * 8 + t4 * 2;
        av[t][0] = alv[col]; av[t][1] = alv[col + 1];
        rv[t][0] = arv[col]; rv[t][1] = arv[col + 1];
    }
#pragma unroll
    for (int mi = 0; mi < 2; mi++) {
        float e0 = 0.f, e1 = 0.f, f0 = 0.f, f1 = 0.f;
#pragma unroll
        for (int t = 0; t < 8; t++) {
            e0 += acc[mi][t][0] * av[t][0] + acc[mi][t][1] * av[t][1];
            e1 += acc[mi][t][2] * av[t][0] + acc[mi][t][3] * av[t][1];
            f0 += acc[mi][t][0] * rv[t][0] + acc[mi][t][1] * rv[t][1];
            f1 += acc[mi][t][2] * rv[t][0] + acc[mi][t][3] * rv[t][1];
        }
#pragma unroll
        for (int o = 1; o <= 2; o <<= 1) {
            e0 += __shfl_xor_sync(0xffffffffu, e0, o);
            e1 += __shfl_xor_sync(0xffffffffu, e1, o);
            f0 += __shfl_xor_sync(0xffffffffu, f0, o);
            f1 += __shfl_xor_sync(0xffffffffu, f1, o);
        }
        if (t4 == 0) {
            int r0 = baseM + wm * 32 + mi * 16 + g;
            int r1 = r0 + 8;
            if (r0 < n) { atomicAdd(&elo[r0 * 4 + hh], e0); atomicAdd(&ero[r0 * 4 + hh], f0); }
            if (r1 < n) { atomicAdd(&elo[r1 * 4 + hh], e1); atomicAdd(&ero[r1 * 4 + hh], f1); }
        }
    }
}

// --------- small GEMM for layer 2 (kin=256, kout=16) + fused el/er ----------
__global__ void __launch_bounds__(512) gemm16(
    const float* __restrict__ A, const float* __restrict__ W,
    float* __restrict__ C, int n,
    const float* __restrict__ alv, const float* __restrict__ arv,
    float* __restrict__ elo, float* __restrict__ ero) {
    __shared__ float As[32][256];
    __shared__ float Wt[16][260];
    int tid = threadIdx.x;
    int base = blockIdx.x * 32;
    for (int i = tid; i < 4096; i += 512) {
        int k = i >> 4, oi = i & 15;
        Wt[oi][k] = W[i];
    }
    for (int i = tid; i < 2048; i += 512) {
        int r = i >> 6, c4 = i & 63;
        float4 v = make_float4(0.f, 0.f, 0.f, 0.f);
        if (base + r < n) v = ((const float4*)(A + (size_t)(base + r) * 256))[c4];
        ((float4*)&As[r][0])[c4] = v;
    }
    __syncthreads();
    int ni = tid >> 4, oi = tid & 15;
    float acc = 0.f;
#pragma unroll 16
    for (int k4 = 0; k4 < 64; k4++) {
        float4 a = ((const float4*)&As[ni][0])[k4];
        float4 w = *(const float4*)&Wt[oi][k4 * 4];
        acc += a.x * w.x + a.y * w.y + a.z * w.z + a.w * w.w;
    }
    if (base + ni < n) C[(size_t)(base + ni) * 16 + oi] = acc;

    float e = acc * alv[oi], f = acc * arv[oi];
#pragma unroll
    for (int o = 8; o; o >>= 1) {
        e += __shfl_xor_sync(0xffffffffu, e, o);
        f += __shfl_xor_sync(0xffffffffu, f, o);
    }
    if (oi == 0 && base + ni < n) { elo[base + ni] = e; ero[base + ni] = f; }
}

// ---- fused softmax + aggregate, H=4, D=64 (ebuf-free, unroll x2: FINAL) ----
template <int OUT_BF16>
__global__ void __launch_bounds__(256) gat_fused4(
    const int* __restrict__ rp, const int* __restrict__ cs,
    const float* __restrict__ el, const float* __restrict__ er,
    const float* __restrict__ feat, const float* __restrict__ bias,
    float* __restrict__ outf,
    __nv_bfloat16* __restrict__ outhi, __nv_bfloat16* __restrict__ outlo)
{
    int node = (blockIdx.x * blockDim.x + threadIdx.x) >> 5;
    int lane = threadIdx.x & 31;
    if (node >= NN) return;
    int s0 = rp[node], s1 = rp[node + 1];

    float4 er4 = *(const float4*)&er[node * 4];

    float t0 = 0.f, t1 = 0.f, t2 = 0.f, t3 = 0.f;
    for (int i = s0 + lane; i < s1; i += 32) {
        int sn = cs[i];
        float4 lv = *(const float4*)&el[sn * 4];
        lv.x += er4.x; lv.y += er4.y; lv.z += er4.z; lv.w += er4.w;
        lv.x = lv.x > 0.f ? lv.x : 0.2f * lv.x;
        lv.y = lv.y > 0.f ? lv.y : 0.2f * lv.y;
        lv.z = lv.z > 0.f ? lv.z : 0.2f * lv.z;
        lv.w = lv.w > 0.f ? lv.w : 0.2f * lv.w;
        t0 += __expf(lv.x); t1 += __expf(lv.y);
        t2 += __expf(lv.z); t3 += __expf(lv.w);
    }
#pragma unroll
    for (int o = 16; o; o >>= 1) {
        t0 += __shfl_xor_sync(0xffffffffu, t0, o);
        t1 += __shfl_xor_sync(0xffffffffu, t1, o);
        t2 += __shfl_xor_sync(0xffffffffu, t2, o);
        t3 += __shfl_xor_sync(0xffffffffu, t3, o);
    }

    int hl = lane >> 3;
    float sv = hl == 0 ? t0 : hl == 1 ? t1 : hl == 2 ? t2 : t3;
    float erh = hl == 0 ? er4.x : hl == 1 ? er4.y : hl == 2 ? er4.z : er4.w;
    float inv = 1.f / sv;

    float a0 = 0.f, a1 = 0.f, a2 = 0.f, a3 = 0.f, a4 = 0.f, a5 = 0.f, a6 = 0.f, a7 = 0.f;
    int i = s0;
    for (; i + 2 <= s1; i += 2) {
        int sn0 = cs[i], sn1 = cs[i + 1];
        float x0 = el[sn0 * 4 + hl] + erh;
        float x1 = el[sn1 * 4 + hl] + erh;
        x0 = x0 > 0.f ? x0 : 0.2f * x0;
        x1 = x1 > 0.f ? x1 : 0.2f * x1;
        float aa0 = __expf(x0) * inv;
        float aa1 = __expf(x1) * inv;
        const float4* fp0 = (const float4*)(feat + (size_t)sn0 * 256 + lane * 8);
        const float4* fp1 = (const float4*)(feat + (size_t)sn1 * 256 + lane * 8);
        float4 u0 = fp0[0], u1 = fp0[1];
        float4 w0 = fp1[0], w1 = fp1[1];
        a0 += aa0 * u0.x + aa1 * w0.x; a1 += aa0 * u0.y + aa1 * w0.y;
        a2 += aa0 * u0.z + aa1 * w0.z; a3 += aa0 * u0.w + aa1 * w0.w;
        a4 += aa0 * u1.x + aa1 * w1.x; a5 += aa0 * u1.y + aa1 * w1.y;
        a6 += aa0 * u1.z + aa1 * w1.z; a7 += aa0 * u1.w + aa1 * w1.w;
    }
    if (i < s1) {
        int sn = cs[i];
        float x = el[sn * 4 + hl] + erh;
        x = x > 0.f ? x : 0.2f * x;
        float a = __expf(x) * inv;
        const float4* fp = (const float4*)(feat + (size_t)sn * 256 + lane * 8);
        float4 v0 = fp[0], v1 = fp[1];
        a0 += a * v0.x; a1 += a * v0.y; a2 += a * v0.z; a3 += a * v0.w;
        a4 += a * v1.x; a5 += a * v1.y; a6 += a * v1.z; a7 += a * v1.w;
    }
    const float4* bp = (const float4*)(bias + lane * 8);
    float4 b0 = bp[0], b1 = bp[1];
    float r[8] = { a0 + b0.x, a1 + b0.y, a2 + b0.z, a3 + b0.w,
                   a4 + b1.x, a5 + b1.y, a6 + b1.z, a7 + b1.w };
    if (OUT_BF16) {
        __nv_bfloat16 hi[8], lo[8];
#pragma unroll
        for (int q = 0; q < 8; q++) {
            hi[q] = __float2bfloat16(r[q]);
            lo[q] = __float2bfloat16(r[q] - __bfloat162float(hi[q]));
        }
        *(uint4*)(outhi + (size_t)node * 256 + lane * 8) = *(const uint4*)hi;
        *(uint4*)(outlo + (size_t)node * 256 + lane * 8) = *(const uint4*)lo;
    } else {
        float4* op = (float4*)(outf + (size_t)node * 256 + lane * 8);
        op[0] = make_float4(r[0], r[1], r[2], r[3]);
        op[1] = make_float4(r[4], r[5], r[6], r[7]);
    }
}

// ---- fused softmax + aggregate, H=1, D=16 (ebuf-free) ----------------------
__global__ void __launch_bounds__(256) gat_fused1(
    const int* __restrict__ rp, const int* __restrict__ cs,
    const float* __restrict__ el, const float* __restrict__ er,
    const float* __restrict__ feat, const float* __restrict__ bias,
    float* __restrict__ out)
{
    int warp = (blockIdx.x * blockDim.x + threadIdx.x) >> 5;
    int lane = threadIdx.x & 31;
    if (warp >= NN) return;
    int s0 = rp[warp], s1 = rp[warp + 1];
    float erv = er[warp];

    float t = 0.f;
    for (int i = s0 + lane; i < s1; i += 32) {
        float x = el[cs[i]] + erv;
        x = x > 0.f ? x : 0.2f * x;
        t += __expf(x);
    }
#pragma unroll
    for (int o = 16; o; o >>= 1) t += __shfl_xor_sync(0xffffffffu, t, o);
    float inv = 1.f / t;

    int half = lane >> 4, dk = lane & 15;
    float acc = 0.f;
    for (int i = s0 + half; i < s1; i += 2) {
        int sn = cs[i];
        float x = el[sn] + erv;
        x = x > 0.f ? x : 0.2f * x;
        float a = __expf(x) * inv;
        acc += a * feat[(size_t)sn * 16 + dk];
    }
    acc += __shfl_xor_sync(0xffffffffu, acc, 16);
    if (lane < 16) out[(size_t)warp * 16 + lane] = acc + bias[lane];
}

// ---------------------------------------------------------------------------
extern "C" void kernel_launch(void* const* d_in, const int* in_sizes, int n_in,
                              void* d_out, int out_size) {
    const float* inputs = (const float*)d_in[0];
    const float* W0 = (const float*)d_in[1];
    const float* al0 = (const float*)d_in[2];
    const float* ar0 = (const float*)d_in[3];
    const float* b0 = (const float*)d_in[4];
    const float* W1 = (const float*)d_in[5];
    const float* al1 = (const float*)d_in[6];
    const float* ar1 = (const float*)d_in[7];
    const float* b1 = (const float*)d_in[8];
    const float* W2 = (const float*)d_in[9];
    const float* al2 = (const float*)d_in[10];
    const float* ar2 = (const float*)d_in[11];
    const float* b2 = (const float*)d_in[12];
    const int* src = (const int*)d_in[13];
    const int* dst = (const int*)d_in[14];

    float *feat, *h, *elA, *erA, *elB, *erB;
    int *cnt, *rpp, *cur, *csrc, *bsum;
    __nv_bfloat16 *Ahi, *Alo, *Whi, *Wlo, *Whi2, *Wlo2;
    cudaGetSymbolAddress((void**)&feat, g_feat);
    cudaGetSymbolAddress((void**)&h, g_h);
    cudaGetSymbolAddress((void**)&elA, g_el);
    cudaGetSymbolAddress((void**)&erA, g_er);
    cudaGetSymbolAddress((void**)&elB, g_el2);
    cudaGetSymbolAddress((void**)&erB, g_er2);
    cudaGetSymbolAddress((void**)&cnt, g_cnt);
    cudaGetSymbolAddress((void**)&rpp, g_rp);
    cudaGetSymbolAddress((void**)&cur, g_cur);
    cudaGetSymbolAddress((void**)&csrc, g_csrc);
    cudaGetSymbolAddress((void**)&bsum, g_bsum);
    cudaGetSymbolAddress((void**)&Ahi, g_Ahi);
    cudaGetSymbolAddress((void**)&Alo, g_Alo);
    cudaGetSymbolAddress((void**)&Whi, g_Whi);
    cudaGetSymbolAddress((void**)&Wlo, g_Wlo);
    cudaGetSymbolAddress((void**)&Whi2, g_Whi2);
    cudaGetSymbolAddress((void**)&Wlo2, g_Wlo2);

    cudaFuncSetAttribute(hmma_gemm, cudaFuncAttributeMaxDynamicSharedMemorySize, HMMA_SMEM);

    int warpBlocks = (NN * 32 + 255) / 256;
    dim3 mmaGrid(1, (NN + 127) / 128);

    cudaStream_t sB;
    cudaEvent_t evFork, evCSR, evW1;
    cudaStreamCreateWithFlags(&sB, cudaStreamNonBlocking);
    cudaEventCreateWithFlags(&evFork, cudaEventDisableTiming);
    cudaEventCreateWithFlags(&evCSR, cudaEventDisableTiming);
    cudaEventCreateWithFlags(&evW1, cudaEventDisableTiming);

    cudaEventRecord(evFork, 0);
    cudaStreamWaitEvent(sB, evFork, 0);

    // ---- side stream: CSR build, then convW for layer 1 --------------------
    init_cnt<<<(NN + 255) / 256, 256, 0, sB>>>(cnt);
    hist_kernel<<<(NE + 255) / 256, 256, 0, sB>>>(dst, cnt);
    scan_p1<<<SCAN_BLOCKS, 256, 0, sB>>>(cnt, bsum);
    scan_p2<<<1, 256, 0, sB>>>(bsum);
    scan_p3<<<SCAN_BLOCKS, 32, 0, sB>>>(cnt, bsum, rpp, cur);
    scatter_kernel<<<(NE + 255) / 256, 256, 0, sB>>>(src, dst, cur, csrc);
    cudaEventRecord(evCSR, sB);
    convW_kernel<<<(256 * 256 + 255) / 256, 256, 0, sB>>>(W1, Whi2, Wlo2, 256, elB, erB);
    cudaEventRecord(evW1, sB);

    // ---- main: layer-0 dense path (merged conv kernel) ---------------------
    convAW_kernel<<<(NN * 128 / 4 + 255) / 256, 256>>>(inputs, Ahi, Alo, NN * 128 / 4,
                                                       W0, Whi, Wlo, 128, elA, erA);
    hmma_gemm<<<mmaGrid, 512, HMMA_SMEM>>>(Ahi, Alo, Whi, Wlo, feat, NN, 128,
                                           al0, ar0, elA, erA);
    cudaStreamWaitEvent(0, evCSR, 0);
    gat_fused4<1><<<warpBlocks, 256>>>(rpp, csrc, elA, erA, feat, b0,
                                       nullptr, Ahi, Alo);

    // ---- layer 1 ------------------------------------------------------------
    cudaStreamWaitEvent(0, evW1, 0);
    hmma_gemm<<<mmaGrid, 512, HMMA_SMEM>>>(Ahi, Alo, Whi2, Wlo2, feat, NN, 256,
                                           al1, ar1, elB, erB);
    gat_fused4<0><<<warpBlocks, 256>>>(rpp, csrc, elB, erB, feat, b1,
                                       h, nullptr, nullptr);

    // ---- layer 2 ------------------------------------------------------------
    float* out = (float*)d_out;
    gemm16<<<(NN + 31) / 32, 512>>>(h, W2, feat, NN, al2, ar2, elA, erA);
    gat_fused1<<<warpBlocks, 256>>>(rpp, csrc, elA, erA, feat, b2, out);

    cudaEventDestroy(evFork);
    cudaEventDestroy(evCSR);
    cudaEventDestroy(evW1);
    cudaStreamDestroy(sB);
}